// round 1
// baseline (speedup 1.0000x reference)
#include <cuda_runtime.h>
#include <cuda_bf16.h>

// Problem constants (fixed by reference setup)
#define N_NODES 50000
#define N_EDGES 600000
#define DFEAT   128
#define N_ETYPE 4
#define N_STEPS 5

// ---------------------------------------------------------------------------
// Device scratch (static __device__ arrays: allocation-free, graph-safe)
// ---------------------------------------------------------------------------
__device__ float g_t[(long)N_ETYPE * N_NODES * DFEAT];   // per-type transformed feats, 102.4 MB
__device__ float g_a[(long)N_NODES * DFEAT];             // aggregated messages, 25.6 MB
__device__ float g_h[(long)N_NODES * DFEAT];             // hidden state, 25.6 MB
__device__ float g_gi[(long)N_NODES * 3 * DFEAT];        // a @ w_ih^T + b_ih, 76.8 MB
__device__ float g_gh[(long)N_NODES * 3 * DFEAT];        // h @ w_hh^T + b_hh, 76.8 MB

// ---------------------------------------------------------------------------
// Tiled fp32 GEMM:  C[n][f] = sum_d X[n][d] * W[f][d] + bias[f]
//   X: [nrows, 128], W: [F, 128] row-major, C: [nrows, F]
//   grid: (ceil(nrows/64), F/128, batch)  — batch strides passed explicitly
//   Tile: 64 rows x 128 cols, k-chunks of 64.
//   smem: As[d][m] (64x68 transposed, float4-friendly A reads),
//         Bs[d][f] (64x132).
//   Microtile per thread: 4 rows x (4 + 4) cols (split-column to limit
//   LDS bank conflicts to 2-way on the B operand).
// ---------------------------------------------------------------------------
#define GEMM_SMEM_BYTES (64 * 68 * 4 + 64 * 132 * 4)   // 17408 + 33792 = 51200

__global__ void __launch_bounds__(256) gemm_bias_kernel(
    const float* __restrict__ X, const float* __restrict__ W,
    const float* __restrict__ bias, float* __restrict__ C,
    int nrows, int F, long w_bstride, long c_bstride, int bias_bstride)
{
    extern __shared__ float sm[];
    float (*As)[68]  = (float (*)[68])sm;              // [64][68]  As[d][m]
    float (*Bs)[132] = (float (*)[132])(sm + 64 * 68); // [64][132] Bs[d][f]

    const int rt = blockIdx.x;
    const int ct = blockIdx.y;
    const int bz = blockIdx.z;

    const float* Wb = W + (long)bz * w_bstride + (long)ct * 128 * DFEAT;
    const float* bb = bias + (long)bz * bias_bstride + ct * 128;
    float*       Cb = C + (long)bz * c_bstride;

    const int t  = threadIdx.x;
    const int tx = t & 15;      // 0..15 -> column groups
    const int ty = t >> 4;      // 0..15 -> row groups
    const int row0 = rt * 64;

    float acc[4][8];
#pragma unroll
    for (int i = 0; i < 4; i++)
#pragma unroll
        for (int j = 0; j < 8; j++) acc[i][j] = 0.f;

    for (int kc = 0; kc < 128; kc += 64) {
        // Load A tile transposed: X[row0+m][kc+d] -> As[d][m]
#pragma unroll
        for (int i = 0; i < 16; i++) {
            int idx = t + i * 256;          // 0..4095
            int m = idx >> 6, d = idx & 63;
            int row = row0 + m;
            As[d][m] = (row < nrows) ? X[(long)row * DFEAT + kc + d] : 0.f;
        }
        // Load B tile transposed: Wb[f][kc+d] -> Bs[d][f]
#pragma unroll
        for (int i = 0; i < 32; i++) {
            int idx = t + i * 256;          // 0..8191
            int f = idx >> 6, d = idx & 63;
            Bs[d][f] = Wb[f * DFEAT + kc + d];
        }
        __syncthreads();

#pragma unroll
        for (int d = 0; d < 64; d++) {
            float4 ra = *(const float4*)&As[d][ty * 4];
            float rb[8];
            *(float4*)&rb[0] = *(const float4*)&Bs[d][tx * 4];
            *(float4*)&rb[4] = *(const float4*)&Bs[d][64 + tx * 4];
            float av[4] = {ra.x, ra.y, ra.z, ra.w};
#pragma unroll
            for (int i = 0; i < 4; i++)
#pragma unroll
                for (int j = 0; j < 8; j++)
                    acc[i][j] += av[i] * rb[j];
        }
        __syncthreads();
    }

    // Epilogue: bias + store (split columns: tx*4 and 64+tx*4)
    float bv[8];
#pragma unroll
    for (int j = 0; j < 4; j++) {
        bv[j]     = bb[tx * 4 + j];
        bv[4 + j] = bb[64 + tx * 4 + j];
    }
#pragma unroll
    for (int i = 0; i < 4; i++) {
        int row = row0 + ty * 4 + i;
        if (row < nrows) {
            long base = (long)row * F + (long)ct * 128;
            float4 v0 = make_float4(acc[i][0] + bv[0], acc[i][1] + bv[1],
                                    acc[i][2] + bv[2], acc[i][3] + bv[3]);
            float4 v1 = make_float4(acc[i][4] + bv[4], acc[i][5] + bv[5],
                                    acc[i][6] + bv[6], acc[i][7] + bv[7]);
            *(float4*)&Cb[base + tx * 4]      = v0;
            *(float4*)&Cb[base + 64 + tx * 4] = v1;
        }
    }
}

// ---------------------------------------------------------------------------
// Edge scatter: a[dst[e]] += t[etype[e]-1][src[e]]   (warp per edge)
// ---------------------------------------------------------------------------
__global__ void __launch_bounds__(256) scatter_kernel(
    const int* __restrict__ src, const int* __restrict__ dst,
    const int* __restrict__ ety,
    const float* __restrict__ tmat, float* __restrict__ a)
{
    int gid  = blockIdx.x * 256 + threadIdx.x;
    int e    = gid >> 5;
    int lane = gid & 31;
    if (e >= N_EDGES) return;
    int s = src[e];
    int d = dst[e];
    int k = ety[e] - 1;

    const float4 v = *(const float4*)&tmat[((long)k * N_NODES + s) * DFEAT + lane * 4];
    float* ap = &a[(long)d * DFEAT + lane * 4];
    atomicAdd(ap + 0, v.x);
    atomicAdd(ap + 1, v.y);
    atomicAdd(ap + 2, v.z);
    atomicAdd(ap + 3, v.w);
}

// ---------------------------------------------------------------------------
// GRU gate elementwise: h_out = (1-z)*n + z*h
// ---------------------------------------------------------------------------
__global__ void __launch_bounds__(256) gru_gate_kernel(
    const float* __restrict__ gi, const float* __restrict__ gh,
    const float* __restrict__ hin, float* __restrict__ hout)
{
    int idx = blockIdx.x * 256 + threadIdx.x;   // over N_NODES*DFEAT = 6.4M
    if (idx >= N_NODES * DFEAT) return;
    int n = idx >> 7;
    int i = idx & 127;
    const float* gin = gi + (long)n * 384;
    const float* ghn = gh + (long)n * 384;

    float ir = gin[i],       hr = ghn[i];
    float iz = gin[128 + i], hz = ghn[128 + i];
    float in_ = gin[256 + i], hn = ghn[256 + i];

    float r  = 1.f / (1.f + __expf(-(ir + hr)));
    float z  = 1.f / (1.f + __expf(-(iz + hz)));
    float nn = tanhf(in_ + r * hn);
    hout[idx] = (1.f - z) * nn + z * hin[idx];
}

// ---------------------------------------------------------------------------
// Launch
// ---------------------------------------------------------------------------
extern "C" void kernel_launch(void* const* d_in, const int* in_sizes, int n_in,
                              void* d_out, int out_size)
{
    const float* h_in  = (const float*)d_in[0];
    const int*   src   = (const int*)d_in[1];
    const int*   dst   = (const int*)d_in[2];
    const int*   ety   = (const int*)d_in[3];
    const float* W_lin = (const float*)d_in[4];
    const float* b_lin = (const float*)d_in[5];
    const float* w_ih  = (const float*)d_in[6];
    const float* w_hh  = (const float*)d_in[7];
    const float* b_ih  = (const float*)d_in[8];
    const float* b_hh  = (const float*)d_in[9];

    float *t_p, *a_p, *h_p, *gi_p, *gh_p;
    cudaGetSymbolAddress((void**)&t_p,  g_t);
    cudaGetSymbolAddress((void**)&a_p,  g_a);
    cudaGetSymbolAddress((void**)&h_p,  g_h);
    cudaGetSymbolAddress((void**)&gi_p, g_gi);
    cudaGetSymbolAddress((void**)&gh_p, g_gh);

    cudaFuncSetAttribute(gemm_bias_kernel,
                         cudaFuncAttributeMaxDynamicSharedMemorySize,
                         GEMM_SMEM_BYTES);

    // h <- input hidden state
    cudaMemcpyAsync(h_p, h_in, (size_t)N_NODES * DFEAT * sizeof(float),
                    cudaMemcpyDeviceToDevice);

    const int row_tiles = (N_NODES + 63) / 64;   // 782

    for (int step = 0; step < N_STEPS; step++) {
        // 1) per-type transforms: t[k] = h @ W_lin[k]^T + b_lin[k]
        gemm_bias_kernel<<<dim3(row_tiles, 1, N_ETYPE), 256, GEMM_SMEM_BYTES>>>(
            h_p, W_lin, b_lin, t_p,
            N_NODES, 128,
            (long)128 * 128,               // W batch stride
            (long)N_NODES * 128,           // C batch stride
            128);                          // bias batch stride

        // 2) aggregate: a = segment_sum(t[et, src], dst)
        cudaMemsetAsync(a_p, 0, (size_t)N_NODES * DFEAT * sizeof(float));
        scatter_kernel<<<(N_EDGES * 32 + 255) / 256, 256>>>(src, dst, ety, t_p, a_p);

        // 3) GRU gates
        gemm_bias_kernel<<<dim3(row_tiles, 3, 1), 256, GEMM_SMEM_BYTES>>>(
            a_p, w_ih, b_ih, gi_p, N_NODES, 384, 0, 0, 0);
        gemm_bias_kernel<<<dim3(row_tiles, 3, 1), 256, GEMM_SMEM_BYTES>>>(
            h_p, w_hh, b_hh, gh_p, N_NODES, 384, 0, 0, 0);

        float* hout = (step == N_STEPS - 1) ? (float*)d_out : h_p;
        gru_gate_kernel<<<(N_NODES * DFEAT + 255) / 256, 256>>>(gi_p, gh_p, h_p, hout);
    }
}

// round 2
// speedup vs baseline: 1.0008x; 1.0008x over previous
#include <cuda_runtime.h>
#include <cuda_bf16.h>

// Problem constants (fixed by reference setup)
#define N_NODES 50000
#define N_EDGES 600000
#define DFEAT   128
#define N_ETYPE 4
#define N_STEPS 5

// ---------------------------------------------------------------------------
// Device scratch (static __device__ arrays: allocation-free, graph-safe)
// ---------------------------------------------------------------------------
__device__ float g_t[(long)N_ETYPE * N_NODES * DFEAT];   // per-type transformed feats, 102.4 MB
__device__ float g_a[(long)N_NODES * DFEAT];             // aggregated messages, 25.6 MB
__device__ float g_h[(long)N_NODES * DFEAT];             // hidden state, 25.6 MB
__device__ float g_gi[(long)N_NODES * 3 * DFEAT];        // a @ w_ih^T + b_ih, 76.8 MB
__device__ float g_gh[(long)N_NODES * 3 * DFEAT];        // h @ w_hh^T + b_hh, 76.8 MB

// ---------------------------------------------------------------------------
// Tiled fp32 GEMM:  C[n][f] = sum_d X[n][d] * W[f][d] + bias[f]
//   X: [nrows, 128], W: [F, 128] row-major, C: [nrows, F]
//   grid: (ceil(nrows/64), F/128, batch)  — batch strides passed explicitly
//   Tile: 64 rows x 128 cols, k-chunks of 64.
//   smem: As[d][m] (64x68 transposed, float4-friendly A reads),
//         Bs[d][f] (64x132).
//   Microtile per thread: 4 rows x (4 + 4) cols (split-column to limit
//   LDS bank conflicts to 2-way on the B operand).
// ---------------------------------------------------------------------------
#define GEMM_SMEM_BYTES (64 * 68 * 4 + 64 * 132 * 4)   // 17408 + 33792 = 51200

__global__ void __launch_bounds__(256) gemm_bias_kernel(
    const float* __restrict__ X, const float* __restrict__ W,
    const float* __restrict__ bias, float* __restrict__ C,
    int nrows, int F, long w_bstride, long c_bstride, int bias_bstride)
{
    extern __shared__ float sm[];
    float (*As)[68]  = (float (*)[68])sm;              // [64][68]  As[d][m]
    float (*Bs)[132] = (float (*)[132])(sm + 64 * 68); // [64][132] Bs[d][f]

    const int rt = blockIdx.x;
    const int ct = blockIdx.y;
    const int bz = blockIdx.z;

    const float* Wb = W + (long)bz * w_bstride + (long)ct * 128 * DFEAT;
    const float* bb = bias + (long)bz * bias_bstride + ct * 128;
    float*       Cb = C + (long)bz * c_bstride;

    const int t  = threadIdx.x;
    const int tx = t & 15;      // 0..15 -> column groups
    const int ty = t >> 4;      // 0..15 -> row groups
    const int row0 = rt * 64;

    float acc[4][8];
#pragma unroll
    for (int i = 0; i < 4; i++)
#pragma unroll
        for (int j = 0; j < 8; j++) acc[i][j] = 0.f;

    for (int kc = 0; kc < 128; kc += 64) {
        // Load A tile transposed: X[row0+m][kc+d] -> As[d][m]
#pragma unroll
        for (int i = 0; i < 16; i++) {
            int idx = t + i * 256;          // 0..4095
            int m = idx >> 6, d = idx & 63;
            int row = row0 + m;
            As[d][m] = (row < nrows) ? X[(long)row * DFEAT + kc + d] : 0.f;
        }
        // Load B tile transposed: Wb[f][kc+d] -> Bs[d][f]
#pragma unroll
        for (int i = 0; i < 32; i++) {
            int idx = t + i * 256;          // 0..8191
            int f = idx >> 6, d = idx & 63;
            Bs[d][f] = Wb[f * DFEAT + kc + d];
        }
        __syncthreads();

#pragma unroll
        for (int d = 0; d < 64; d++) {
            float4 ra = *(const float4*)&As[d][ty * 4];
            float rb[8];
            *(float4*)&rb[0] = *(const float4*)&Bs[d][tx * 4];
            *(float4*)&rb[4] = *(const float4*)&Bs[d][64 + tx * 4];
            float av[4] = {ra.x, ra.y, ra.z, ra.w};
#pragma unroll
            for (int i = 0; i < 4; i++)
#pragma unroll
                for (int j = 0; j < 8; j++)
                    acc[i][j] += av[i] * rb[j];
        }
        __syncthreads();
    }

    // Epilogue: bias + store (split columns: tx*4 and 64+tx*4)
    float bv[8];
#pragma unroll
    for (int j = 0; j < 4; j++) {
        bv[j]     = bb[tx * 4 + j];
        bv[4 + j] = bb[64 + tx * 4 + j];
    }
#pragma unroll
    for (int i = 0; i < 4; i++) {
        int row = row0 + ty * 4 + i;
        if (row < nrows) {
            long base = (long)row * F + (long)ct * 128;
            float4 v0 = make_float4(acc[i][0] + bv[0], acc[i][1] + bv[1],
                                    acc[i][2] + bv[2], acc[i][3] + bv[3]);
            float4 v1 = make_float4(acc[i][4] + bv[4], acc[i][5] + bv[5],
                                    acc[i][6] + bv[6], acc[i][7] + bv[7]);
            *(float4*)&Cb[base + tx * 4]      = v0;
            *(float4*)&Cb[base + 64 + tx * 4] = v1;
        }
    }
}

// ---------------------------------------------------------------------------
// Edge scatter: a[dst[e]] += t[etype[e]-1][src[e]]   (warp per edge)
// ---------------------------------------------------------------------------
__global__ void __launch_bounds__(256) scatter_kernel(
    const int* __restrict__ src, const int* __restrict__ dst,
    const int* __restrict__ ety,
    const float* __restrict__ tmat, float* __restrict__ a)
{
    int gid  = blockIdx.x * 256 + threadIdx.x;
    int e    = gid >> 5;
    int lane = gid & 31;
    if (e >= N_EDGES) return;
    int s = src[e];
    int d = dst[e];
    int k = ety[e] - 1;

    const float4 v = *(const float4*)&tmat[((long)k * N_NODES + s) * DFEAT + lane * 4];
    float* ap = &a[(long)d * DFEAT + lane * 4];
    atomicAdd(ap + 0, v.x);
    atomicAdd(ap + 1, v.y);
    atomicAdd(ap + 2, v.z);
    atomicAdd(ap + 3, v.w);
}

// ---------------------------------------------------------------------------
// GRU gate elementwise: h_out = (1-z)*n + z*h
// ---------------------------------------------------------------------------
__global__ void __launch_bounds__(256) gru_gate_kernel(
    const float* __restrict__ gi, const float* __restrict__ gh,
    const float* __restrict__ hin, float* __restrict__ hout)
{
    int idx = blockIdx.x * 256 + threadIdx.x;   // over N_NODES*DFEAT = 6.4M
    if (idx >= N_NODES * DFEAT) return;
    int n = idx >> 7;
    int i = idx & 127;
    const float* gin = gi + (long)n * 384;
    const float* ghn = gh + (long)n * 384;

    float ir = gin[i],       hr = ghn[i];
    float iz = gin[128 + i], hz = ghn[128 + i];
    float in_ = gin[256 + i], hn = ghn[256 + i];

    float r  = 1.f / (1.f + __expf(-(ir + hr)));
    float z  = 1.f / (1.f + __expf(-(iz + hz)));
    float nn = tanhf(in_ + r * hn);
    hout[idx] = (1.f - z) * nn + z * hin[idx];
}

// ---------------------------------------------------------------------------
// Launch
// ---------------------------------------------------------------------------
extern "C" void kernel_launch(void* const* d_in, const int* in_sizes, int n_in,
                              void* d_out, int out_size)
{
    const float* h_in  = (const float*)d_in[0];
    const int*   src   = (const int*)d_in[1];
    const int*   dst   = (const int*)d_in[2];
    const int*   ety   = (const int*)d_in[3];
    const float* W_lin = (const float*)d_in[4];
    const float* b_lin = (const float*)d_in[5];
    const float* w_ih  = (const float*)d_in[6];
    const float* w_hh  = (const float*)d_in[7];
    const float* b_ih  = (const float*)d_in[8];
    const float* b_hh  = (const float*)d_in[9];

    float *t_p, *a_p, *h_p, *gi_p, *gh_p;
    cudaGetSymbolAddress((void**)&t_p,  g_t);
    cudaGetSymbolAddress((void**)&a_p,  g_a);
    cudaGetSymbolAddress((void**)&h_p,  g_h);
    cudaGetSymbolAddress((void**)&gi_p, g_gi);
    cudaGetSymbolAddress((void**)&gh_p, g_gh);

    cudaFuncSetAttribute(gemm_bias_kernel,
                         cudaFuncAttributeMaxDynamicSharedMemorySize,
                         GEMM_SMEM_BYTES);

    // h <- input hidden state
    cudaMemcpyAsync(h_p, h_in, (size_t)N_NODES * DFEAT * sizeof(float),
                    cudaMemcpyDeviceToDevice);

    const int row_tiles = (N_NODES + 63) / 64;   // 782

    for (int step = 0; step < N_STEPS; step++) {
        // 1) per-type transforms: t[k] = h @ W_lin[k]^T + b_lin[k]
        gemm_bias_kernel<<<dim3(row_tiles, 1, N_ETYPE), 256, GEMM_SMEM_BYTES>>>(
            h_p, W_lin, b_lin, t_p,
            N_NODES, 128,
            (long)128 * 128,               // W batch stride
            (long)N_NODES * 128,           // C batch stride
            128);                          // bias batch stride

        // 2) aggregate: a = segment_sum(t[et, src], dst)
        cudaMemsetAsync(a_p, 0, (size_t)N_NODES * DFEAT * sizeof(float));
        scatter_kernel<<<(N_EDGES * 32 + 255) / 256, 256>>>(src, dst, ety, t_p, a_p);

        // 3) GRU gates
        gemm_bias_kernel<<<dim3(row_tiles, 3, 1), 256, GEMM_SMEM_BYTES>>>(
            a_p, w_ih, b_ih, gi_p, N_NODES, 384, 0, 0, 0);
        gemm_bias_kernel<<<dim3(row_tiles, 3, 1), 256, GEMM_SMEM_BYTES>>>(
            h_p, w_hh, b_hh, gh_p, N_NODES, 384, 0, 0, 0);

        float* hout = (step == N_STEPS - 1) ? (float*)d_out : h_p;
        gru_gate_kernel<<<(N_NODES * DFEAT + 255) / 256, 256>>>(gi_p, gh_p, h_p, hout);
    }
}

// round 4
// speedup vs baseline: 1.9991x; 1.9974x over previous
#include <cuda_runtime.h>
#include <cuda_fp16.h>
#include <cstdint>

#define NN 50000
#define NE 600000
#define NSTEP 5
typedef unsigned short u16; typedef uint32_t u32;

// ---------------- device scratch ----------------
__device__ u16   g_sh[(long)NN*512], g_sl[(long)NN*512];   // s hi/lo planes [N][512]
__device__ u16   g_ahi[(long)NN*128], g_alo[(long)NN*128]; // a hi/lo planes
__device__ u16   g_hhi[(long)NN*128], g_hlo[(long)NN*128]; // h hi/lo planes
__device__ float g_h[(long)NN*128];                        // h fp32
__device__ float g_g[(long)NN*512];                        // gate pre-activations
__device__ float g_cnt[NN*4];
__device__ int   g_deg[NN], g_roff[NN+1], g_cur[NN];
__device__ int   g_srcs[NE], g_ets[NE];
__device__ u16   g_wch[8*8192],  g_wcl[8*8192];            // Wcat chunks (pre-swizzled fp16 hi/lo)
__device__ u16   g_wgh[16*8192], g_wgl[16*8192];           // gate W chunks

// ---------------- helpers ----------------
__device__ __forceinline__ u32 smem_u32(const void* p){
    u32 a; asm("{ .reg .u64 t; cvta.to.shared.u64 t, %1; cvt.u32.u64 %0, t; }":"=r"(a):"l"(p)); return a;
}
__device__ __forceinline__ u32 swz(u32 o){ return o ^ ((o>>3)&0x70); }
__device__ __forceinline__ void hl(float x, u16& h_, u16& l_){
    __half hh = __float2half_rn(x);
    __half ll = __float2half_rn(x - __half2float(hh));
    h_ = __half_as_ushort(hh); l_ = __half_as_ushort(ll);
}
__device__ __forceinline__ void ldsm4(u32* r, u32 a){
    asm volatile("ldmatrix.sync.aligned.m8n8.x4.shared.b16 {%0,%1,%2,%3}, [%4];"
                 : "=r"(r[0]),"=r"(r[1]),"=r"(r[2]),"=r"(r[3]) : "r"(a));
}
__device__ __forceinline__ void mma16816(float* c, const u32* a, const u32* b){
    asm volatile("mma.sync.aligned.m16n8k16.row.col.f32.f16.f16.f32 "
                 "{%0,%1,%2,%3}, {%4,%5,%6,%7}, {%8,%9}, {%0,%1,%2,%3};"
                 : "+f"(c[0]),"+f"(c[1]),"+f"(c[2]),"+f"(c[3])
                 : "r"(a[0]),"r"(a[1]),"r"(a[2]),"r"(a[3]),"r"(b[0]),"r"(b[1]));
}
__device__ __forceinline__ void cpa(u32 dst, const void* src, int sz){
    asm volatile("cp.async.cg.shared.global [%0], [%1], 16, %2;" :: "r"(dst),"l"(src),"r"(sz) : "memory");
}
#define CP_COMMIT() asm volatile("cp.async.commit_group;" ::: "memory")
#define CP_WAIT1()  asm volatile("cp.async.wait_group 1;" ::: "memory")
#define CP_WAIT0()  asm volatile("cp.async.wait_group 0;" ::: "memory")

// stage layout: Ah@0, Al@16K, Bh@32K, Bl@48K ; stage stride 64K; 2 stages = 128K
#define STAGE 65536
#define SMB   (2*STAGE)

__device__ __forceinline__ void load_a_tile(u32 stage, const u16* __restrict__ SH,
    const u16* __restrict__ SL, int row0, long rstride, int coloff, int t)
{
#pragma unroll
    for (int i=0;i<4;i++){
        int g = t + i*256;
        int r = g>>3, c8 = (g&7)*8;
        int row = row0 + r;
        int ok = (row < NN);
        long ga = (long)(ok?row:0)*rstride + coloff + c8;
        u32 off = swz((u32)(r*128 + c8*2));
        cpa(stage + off,          SH + ga, ok?16:0);
        cpa(stage + 16384 + off,  SL + ga, ok?16:0);
    }
}
__device__ __forceinline__ void load_b_tile(u32 stage, const u16* __restrict__ BH,
    const u16* __restrict__ BL, int chunk, int t)
{
    const uint4* bh = (const uint4*)(BH + (long)chunk*8192);
    const uint4* bl = (const uint4*)(BL + (long)chunk*8192);
#pragma unroll
    for (int i=0;i<4;i++){
        int g = t + i*256;
        cpa(stage + 32768 + g*16, bh+g, 16);
        cpa(stage + 49152 + g*16, bl+g, 16);
    }
}

__device__ __forceinline__ void compute_chunk(u32 sb, float c[4][4][4], int wm, int wn, int lane){
    int arow = wm + (lane&15);
    int akof = (lane>>4)*8;
    int brow = wn + (lane&7) + ((lane&16)>>1);
    int bkof = ((lane>>3)&1)*8;
#pragma unroll
    for (int kb=0;kb<4;kb++){
        u32 ah[4][4], al[4][4], bh[2][4], bl[2][4];
#pragma unroll
        for (int mi=0;mi<4;mi++){
            u32 off = swz((u32)((arow + mi*16)*128 + (kb*16 + akof)*2));
            ldsm4(ah[mi], sb + off);
            ldsm4(al[mi], sb + 16384 + off);
        }
#pragma unroll
        for (int nj=0;nj<2;nj++){
            u32 off = swz((u32)((brow + nj*16)*128 + (kb*16 + bkof)*2));
            ldsm4(bh[nj], sb + 32768 + off);
            ldsm4(bl[nj], sb + 49152 + off);
        }
#pragma unroll
        for (int mi=0;mi<4;mi++)
#pragma unroll
            for (int ni=0;ni<4;ni++){
                int nj = ni>>1, s = (ni&1)*2;
                mma16816(c[mi][ni], ah[mi], bh[nj]+s);
                mma16816(c[mi][ni], al[mi], bh[nj]+s);
                mma16816(c[mi][ni], ah[mi], bl[nj]+s);
            }
    }
}

// ---------------- setup: split + pre-swizzle weights ----------------
__global__ void __launch_bounds__(256) k_setup(const float* __restrict__ W_lin,
    const float* __restrict__ w_ih, const float* __restrict__ w_hh)
{
    for (int idx = blockIdx.x*256+threadIdx.x; idx < 65536+131072; idx += gridDim.x*256){
        float val; u32 dst;
        if (idx < 65536){                        // Wcat: B[f][kg], kg = type*128+d
            int f = idx>>9, kg = idx&511;
            val = W_lin[(kg>>7)*16384 + f*128 + (kg&127)];
            dst = (u32)(kg>>6)*8192 + (swz((u32)(f*128 + (kg&63)*2))>>1);
            u16 hh, ll; hl(val, hh, ll); g_wch[dst]=hh; g_wcl[dst]=ll;
        } else {                                 // gate: nb in {r,z,i_n,h_n}
            int j = idx-65536, nb = j>>15, r = j&32767, f = r>>8, kg = r&255;
            float v = 0.f;
            if (nb==0) v = (kg<128) ? w_ih[f*128+kg]        : w_hh[f*128+kg-128];
            else if (nb==1) v = (kg<128) ? w_ih[(128+f)*128+kg] : w_hh[(128+f)*128+kg-128];
            else if (nb==2) v = (kg<128) ? w_ih[(256+f)*128+kg] : 0.f;
            else            v = (kg<128) ? 0.f : w_hh[(256+f)*128+kg-128];
            val = v;
            dst = (u32)(nb*4 + (kg>>6))*8192 + (swz((u32)(f*128 + (kg&63)*2))>>1);
            u16 hh, ll; hl(val, hh, ll); g_wgh[dst]=hh; g_wgl[dst]=ll;
        }
    }
}

// ---------------- init h ----------------
__global__ void __launch_bounds__(256) k_init(const float* __restrict__ hin){
    int tid = blockIdx.x*256+threadIdx.x;
    if (tid >= NN*64) return;
    float2 v = *(const float2*)&hin[tid*2];
    *(float2*)&g_h[tid*2] = v;
    u16 h0,l0,h1,l1; hl(v.x,h0,l0); hl(v.y,h1,l1);
    *(u32*)&g_hhi[tid*2] = (u32)h0 | ((u32)h1<<16);
    *(u32*)&g_hlo[tid*2] = (u32)l0 | ((u32)l1<<16);
}

// ---------------- CSR build ----------------
__global__ void __launch_bounds__(256) k_hist(const int* __restrict__ dst){
    int e = blockIdx.x*256+threadIdx.x;
    if (e < NE) atomicAdd(&g_deg[dst[e]], 1);
}
__global__ void __launch_bounds__(1024) k_scan(){
    __shared__ int wsum[32]; __shared__ int carry;
    int t = threadIdx.x, lane = t&31, w = t>>5;
    if (t==0) carry = 0;
    __syncthreads();
    for (int base = 0; base < NN; base += 1024){
        int i = base+t;
        int v = (i<NN) ? g_deg[i] : 0;
        int s = v;
        #pragma unroll
        for (int o=1;o<32;o<<=1){ int u=__shfl_up_sync(~0u,s,o); if(lane>=o) s+=u; }
        if (lane==31) wsum[w]=s;
        __syncthreads();
        if (w==0){ int ws=wsum[lane];
            #pragma unroll
            for (int o=1;o<32;o<<=1){ int u=__shfl_up_sync(~0u,ws,o); if(lane>=o) ws+=u; }
            wsum[lane]=ws; }
        __syncthreads();
        int excl = s - v + (w>0 ? wsum[w-1] : 0) + carry;
        if (i<NN){ g_roff[i]=excl; g_cur[i]=excl; }
        __syncthreads();
        if (t==1023) carry = excl + v;
        __syncthreads();
    }
    if (t==0) g_roff[NN] = carry;
}
__global__ void __launch_bounds__(256) k_place(const int* __restrict__ src,
    const int* __restrict__ dst, const int* __restrict__ ety){
    int e = blockIdx.x*256+threadIdx.x;
    if (e >= NE) return;
    int pos = atomicAdd(&g_cur[dst[e]], 1);
    g_srcs[pos] = src[e]; g_ets[pos] = ety[e]-1;
}

// ---------------- s-build: warp per node ----------------
__global__ void __launch_bounds__(256) k_sbuild(){
    int warp = (blockIdx.x*256+threadIdx.x)>>5, lane = threadIdx.x&31;
    if (warp >= NN) return;
    int beg = g_roff[warp], end = g_roff[warp+1];
    float4 a0={0,0,0,0}, a1=a0, a2=a0, a3=a0;
    float c0=0, c1=0, c2=0, c3=0;
    for (int e=beg; e<end; e++){
        int s_ = g_srcs[e], k_ = g_ets[e];
        float4 v = *(const float4*)&g_h[(long)s_*128 + lane*4];
        float m0=(k_==0), m1=(k_==1), m2=(k_==2), m3=(k_==3);
        a0.x=fmaf(m0,v.x,a0.x); a0.y=fmaf(m0,v.y,a0.y); a0.z=fmaf(m0,v.z,a0.z); a0.w=fmaf(m0,v.w,a0.w);
        a1.x=fmaf(m1,v.x,a1.x); a1.y=fmaf(m1,v.y,a1.y); a1.z=fmaf(m1,v.z,a1.z); a1.w=fmaf(m1,v.w,a1.w);
        a2.x=fmaf(m2,v.x,a2.x); a2.y=fmaf(m2,v.y,a2.y); a2.z=fmaf(m2,v.z,a2.z); a2.w=fmaf(m2,v.w,a2.w);
        a3.x=fmaf(m3,v.x,a3.x); a3.y=fmaf(m3,v.y,a3.y); a3.z=fmaf(m3,v.z,a3.z); a3.w=fmaf(m3,v.w,a3.w);
        c0+=m0; c1+=m1; c2+=m2; c3+=m3;
    }
    long base = (long)warp*512 + lane*4;
    float4 acc[4] = {a0,a1,a2,a3};
    #pragma unroll
    for (int k=0;k<4;k++){
        u16 h4[4], l4[4]; const float* f = (const float*)&acc[k];
        #pragma unroll
        for (int i=0;i<4;i++) hl(f[i], h4[i], l4[i]);
        *(uint2*)&g_sh[base + k*128] = *(uint2*)h4;
        *(uint2*)&g_sl[base + k*128] = *(uint2*)l4;
    }
    if (lane==0) *(float4*)&g_cnt[warp*4] = make_float4(c0,c1,c2,c3);
}

// ---------------- GEMM A: a = s @ Wc^T (+cnt.b_lin) -> fp16 planes ----------------
__global__ void __launch_bounds__(256,1) k_gemm_a(const float* __restrict__ b_lin){
    extern __shared__ __align__(1024) char sm[];
    u32 sb = smem_u32(sm);
    int t = threadIdx.x, lane = t&31, wid = t>>5;
    int row0 = blockIdx.x*128;
    int wm = (wid&1)*64, wn = (wid>>1)*32;
    float cacc[4][4][4];
#pragma unroll
    for (int a=0;a<4;a++)
#pragma unroll
        for (int b=0;b<4;b++)
#pragma unroll
            for (int d=0;d<4;d++) cacc[a][b][d]=0.f;

    load_a_tile(sb, g_sh, g_sl, row0, 512, 0, t);
    load_b_tile(sb, g_wch, g_wcl, 0, t);
    CP_COMMIT();
    for (int c=0;c<8;c++){
        u32 st = sb + (u32)(c&1)*STAGE;
        if (c<7){
            u32 nx = sb + (u32)((c+1)&1)*STAGE;
            load_a_tile(nx, g_sh, g_sl, row0, 512, (c+1)*64, t);
            load_b_tile(nx, g_wch, g_wcl, c+1, t);
            CP_COMMIT();
            CP_WAIT1();
        } else CP_WAIT0();
        __syncthreads();
        compute_chunk(st, cacc, wm, wn, lane);
        __syncthreads();
    }
    // epilogue
    float* bls = (float*)sm;
    bls[t] = b_lin[t]; bls[t+256] = b_lin[256+t];
    __syncthreads();
    int tg = (lane&3)*2, gr = lane>>2;
#pragma unroll
    for (int mi=0;mi<4;mi++)
#pragma unroll
        for (int ni=0;ni<4;ni++){
            int col = wn + ni*8 + tg;
#pragma unroll
            for (int hf=0;hf<2;hf++){
                int r2 = row0 + wm + mi*16 + gr + hf*8;
                if (r2 < NN){
                    const float4 cn = *(const float4*)&g_cnt[r2*4];
                    float v0 = cacc[mi][ni][hf*2+0] + cn.x*bls[col]   + cn.y*bls[128+col]
                             + cn.z*bls[256+col]   + cn.w*bls[384+col];
                    float v1 = cacc[mi][ni][hf*2+1] + cn.x*bls[col+1] + cn.y*bls[129+col]
                             + cn.z*bls[257+col]   + cn.w*bls[385+col];
                    u16 h0,l0,h1,l1; hl(v0,h0,l0); hl(v1,h1,l1);
                    *(u32*)&g_ahi[(long)r2*128+col] = (u32)h0 | ((u32)h1<<16);
                    *(u32*)&g_alo[(long)r2*128+col] = (u32)l0 | ((u32)l1<<16);
                }
            }
        }
}

// ---------------- GEMM G: g[:, nb*128..] = [a|h] @ Wg[nb]^T ----------------
__global__ void __launch_bounds__(256,1) k_gemm_g(){
    extern __shared__ __align__(1024) char sm[];
    u32 sb = smem_u32(sm);
    int t = threadIdx.x, lane = t&31, wid = t>>5;
    int row0 = blockIdx.x*128;
    int nb = blockIdx.y;
    int c0 = (nb==3)?2:0, c1 = (nb==2)?2:4;
    int wm = (wid&1)*64, wn = (wid>>1)*32;
    float cacc[4][4][4];
#pragma unroll
    for (int a=0;a<4;a++)
#pragma unroll
        for (int b=0;b<4;b++)
#pragma unroll
            for (int d=0;d<4;d++) cacc[a][b][d]=0.f;

    {
        const u16* SH = (c0<2)? g_ahi : g_hhi;
        const u16* SL = (c0<2)? g_alo : g_hlo;
        load_a_tile(sb, SH, SL, row0, 128, (c0&1)*64, t);
        load_b_tile(sb, g_wgh, g_wgl, nb*4+c0, t);
        CP_COMMIT();
    }
    for (int c=c0;c<c1;c++){
        u32 st = sb + (u32)((c-c0)&1)*STAGE;
        if (c+1<c1){
            u32 nx = sb + (u32)((c+1-c0)&1)*STAGE;
            const u16* SH = (c+1<2)? g_ahi : g_hhi;
            const u16* SL = (c+1<2)? g_alo : g_hlo;
            load_a_tile(nx, SH, SL, row0, 128, ((c+1)&1)*64, t);
            load_b_tile(nx, g_wgh, g_wgl, nb*4+c+1, t);
            CP_COMMIT();
            CP_WAIT1();
        } else CP_WAIT0();
        __syncthreads();
        compute_chunk(st, cacc, wm, wn, lane);
        __syncthreads();
    }
    int tg = (lane&3)*2, gr = lane>>2;
#pragma unroll
    for (int mi=0;mi<4;mi++)
#pragma unroll
        for (int ni=0;ni<4;ni++){
            int col = wn + ni*8 + tg;
#pragma unroll
            for (int hf=0;hf<2;hf++){
                int r2 = row0 + wm + mi*16 + gr + hf*8;
                if (r2 < NN)
                    *(float2*)&g_g[(long)r2*512 + nb*128 + col] =
                        make_float2(cacc[mi][ni][hf*2+0], cacc[mi][ni][hf*2+1]);
            }
        }
}

// ---------------- GRU gates ----------------
__global__ void __launch_bounds__(256) k_gru(const float* __restrict__ b_ih,
    const float* __restrict__ b_hh, float* __restrict__ hout)
{
    int tid = blockIdx.x*256+threadIdx.x;
    if (tid >= NN*64) return;
    int row = tid>>6, p = (tid&63)*2;
    long gb = (long)row*512;
    float2 rp = *(const float2*)&g_g[gb + p];
    float2 zp = *(const float2*)&g_g[gb + 128 + p];
    float2 ip = *(const float2*)&g_g[gb + 256 + p];
    float2 hp = *(const float2*)&g_g[gb + 384 + p];
    float2 hv = *(const float2*)&g_h[(long)row*128 + p];

    float r0 = 1.f/(1.f + __expf(-(rp.x + b_ih[p]   + b_hh[p])));
    float r1 = 1.f/(1.f + __expf(-(rp.y + b_ih[p+1] + b_hh[p+1])));
    float z0 = 1.f/(1.f + __expf(-(zp.x + b_ih[128+p]   + b_hh[128+p])));
    float z1 = 1.f/(1.f + __expf(-(zp.y + b_ih[129+p] + b_hh[129+p])));
    float n0 = tanhf(ip.x + b_ih[256+p]   + r0*(hp.x + b_hh[256+p]));
    float n1 = tanhf(ip.y + b_ih[257+p] + r1*(hp.y + b_hh[257+p]));
    float o0 = (1.f-z0)*n0 + z0*hv.x;
    float o1 = (1.f-z1)*n1 + z1*hv.y;
    *(float2*)&hout[(long)row*128+p] = make_float2(o0,o1);
    u16 h0,l0,h1,l1; hl(o0,h0,l0); hl(o1,h1,l1);
    *(u32*)&g_hhi[(long)row*128+p] = (u32)h0 | ((u32)h1<<16);
    *(u32*)&g_hlo[(long)row*128+p] = (u32)l0 | ((u32)l1<<16);
}

// ---------------- launch ----------------
extern "C" void kernel_launch(void* const* d_in, const int* in_sizes, int n_in,
                              void* d_out, int out_size)
{
    const float* h_in  = (const float*)d_in[0];
    const int*   src   = (const int*)d_in[1];
    const int*   dst   = (const int*)d_in[2];
    const int*   ety   = (const int*)d_in[3];
    const float* W_lin = (const float*)d_in[4];
    const float* b_lin = (const float*)d_in[5];
    const float* w_ih  = (const float*)d_in[6];
    const float* w_hh  = (const float*)d_in[7];
    const float* b_ih  = (const float*)d_in[8];
    const float* b_hh  = (const float*)d_in[9];

    cudaFuncSetAttribute(k_gemm_a, cudaFuncAttributeMaxDynamicSharedMemorySize, SMB);
    cudaFuncSetAttribute(k_gemm_g, cudaFuncAttributeMaxDynamicSharedMemorySize, SMB);

    int* deg_p; cudaGetSymbolAddress((void**)&deg_p, g_deg);
    float* h_p; cudaGetSymbolAddress((void**)&h_p, g_h);

    k_setup<<<768,256>>>(W_lin, w_ih, w_hh);
    k_init<<<(NN*64+255)/256,256>>>(h_in);
    cudaMemsetAsync(deg_p, 0, NN*sizeof(int));
    k_hist<<<(NE+255)/256,256>>>(dst);
    k_scan<<<1,1024>>>();
    k_place<<<(NE+255)/256,256>>>(src, dst, ety);

    const int tiles = (NN+127)/128;   // 391
    for (int step=0; step<NSTEP; step++){
        k_sbuild<<<(NN*32+255)/256,256>>>();
        k_gemm_a<<<tiles,256,SMB>>>(b_lin);
        k_gemm_g<<<dim3(tiles,4),256,SMB>>>();
        float* hout = (step==NSTEP-1) ? (float*)d_out : h_p;
        k_gru<<<(NN*64+255)/256,256>>>(b_ih, b_hh, hout);
    }
    (void)in_sizes; (void)n_in; (void)out_size;
}

// round 5
// speedup vs baseline: 3.6846x; 1.8431x over previous
#include <cuda_runtime.h>
#include <cuda_fp16.h>
#include <cstdint>

#define NN 50000
#define NE 600000
#define NSEG (NN*4)
#define NSTEP 5
typedef unsigned short u16; typedef uint32_t u32;

// ---------------- device scratch ----------------
__device__ u16   g_sh[(long)NN*512], g_sl[(long)NN*512];   // s hi/lo planes [N][512]
__device__ u16   g_ahi[(long)NN*128], g_alo[(long)NN*128]; // a hi/lo planes
__device__ u16   g_hhi[(long)NN*128], g_hlo[(long)NN*128]; // h hi/lo planes
__device__ float g_h[(long)NN*128];                        // h fp32
__device__ float g_g[(long)NN*512];                        // gate pre-activations
__device__ float g_cnt[NSEG];
__device__ int   g_deg[NSEG], g_roff[NSEG+1], g_cur[NSEG];
__device__ int   g_bsum[256], g_boff[256];
__device__ int   g_srcs[NE];
__device__ u16   g_wch[8*8192];                            // Wcat chunks (pre-swizzled fp16)
__device__ u16   g_wgh[16*8192];                           // gate W chunks

// ---------------- helpers ----------------
__device__ __forceinline__ u32 smem_u32(const void* p){
    u32 a; asm("{ .reg .u64 t; cvta.to.shared.u64 t, %1; cvt.u32.u64 %0, t; }":"=r"(a):"l"(p)); return a;
}
__device__ __forceinline__ u32 swz(u32 o){ return o ^ ((o>>3)&0x70); }
__device__ __forceinline__ void hl(float x, u16& h_, u16& l_){
    __half hh = __float2half_rn(x);
    __half ll = __float2half_rn(x - __half2float(hh));
    h_ = __half_as_ushort(hh); l_ = __half_as_ushort(ll);
}
__device__ __forceinline__ void ldsm4(u32* r, u32 a){
    asm volatile("ldmatrix.sync.aligned.m8n8.x4.shared.b16 {%0,%1,%2,%3}, [%4];"
                 : "=r"(r[0]),"=r"(r[1]),"=r"(r[2]),"=r"(r[3]) : "r"(a));
}
__device__ __forceinline__ void mma16816(float* c, const u32* a, const u32* b){
    asm volatile("mma.sync.aligned.m16n8k16.row.col.f32.f16.f16.f32 "
                 "{%0,%1,%2,%3}, {%4,%5,%6,%7}, {%8,%9}, {%0,%1,%2,%3};"
                 : "+f"(c[0]),"+f"(c[1]),"+f"(c[2]),"+f"(c[3])
                 : "r"(a[0]),"r"(a[1]),"r"(a[2]),"r"(a[3]),"r"(b[0]),"r"(b[1]));
}
__device__ __forceinline__ void cpa(u32 dst, const void* src, int sz){
    asm volatile("cp.async.cg.shared.global [%0], [%1], 16, %2;" :: "r"(dst),"l"(src),"r"(sz) : "memory");
}
#define CP_COMMIT() asm volatile("cp.async.commit_group;" ::: "memory")
#define CP_WAIT1()  asm volatile("cp.async.wait_group 1;" ::: "memory")
#define CP_WAIT0()  asm volatile("cp.async.wait_group 0;" ::: "memory")

// stage layout: Ah@0, Al@16K, Bh@32K ; stage stride 48K; 2 stages = 96K
#define STAGE 49152
#define SMB   (2*STAGE)

__device__ __forceinline__ void load_a_tile(u32 stage, const u16* __restrict__ SH,
    const u16* __restrict__ SL, int row0, long rstride, int coloff, int t)
{
#pragma unroll
    for (int i=0;i<4;i++){
        int g = t + i*256;
        int r = g>>3, c8 = (g&7)*8;
        int row = row0 + r;
        int ok = (row < NN);
        long ga = (long)(ok?row:0)*rstride + coloff + c8;
        u32 off = swz((u32)(r*128 + c8*2));
        cpa(stage + off,          SH + ga, ok?16:0);
        cpa(stage + 16384 + off,  SL + ga, ok?16:0);
    }
}
__device__ __forceinline__ void load_b_tile(u32 stage, const u16* __restrict__ BH, int chunk, int t)
{
    const uint4* bh = (const uint4*)(BH + (long)chunk*8192);
#pragma unroll
    for (int i=0;i<4;i++){
        int g = t + i*256;
        cpa(stage + 32768 + g*16, bh+g, 16);
    }
}

__device__ __forceinline__ void compute_chunk(u32 sb, float c[4][4][4], int wm, int wn, int lane){
    int arow = wm + (lane&15);
    int akof = (lane>>4)*8;
    int brow = wn + (lane&7) + ((lane&16)>>1);
    int bkof = ((lane>>3)&1)*8;
#pragma unroll
    for (int kb=0;kb<4;kb++){
        u32 ah[4][4], al[4][4], bh[2][4];
#pragma unroll
        for (int mi=0;mi<4;mi++){
            u32 off = swz((u32)((arow + mi*16)*128 + (kb*16 + akof)*2));
            ldsm4(ah[mi], sb + off);
            ldsm4(al[mi], sb + 16384 + off);
        }
#pragma unroll
        for (int nj=0;nj<2;nj++){
            u32 off = swz((u32)((brow + nj*16)*128 + (kb*16 + bkof)*2));
            ldsm4(bh[nj], sb + 32768 + off);
        }
#pragma unroll
        for (int mi=0;mi<4;mi++)
#pragma unroll
            for (int ni=0;ni<4;ni++){
                int nj = ni>>1, s = (ni&1)*2;
                mma16816(c[mi][ni], ah[mi], bh[nj]+s);
                mma16816(c[mi][ni], al[mi], bh[nj]+s);
            }
    }
}

// ---------------- setup: pre-swizzle fp16 weights ----------------
__global__ void __launch_bounds__(256) k_setup(const float* __restrict__ W_lin,
    const float* __restrict__ w_ih, const float* __restrict__ w_hh)
{
    for (int idx = blockIdx.x*256+threadIdx.x; idx < 65536+131072; idx += gridDim.x*256){
        float val; u32 dst;
        if (idx < 65536){                        // Wcat: B[f][kg], kg = type*128+d
            int f = idx>>9, kg = idx&511;
            val = W_lin[(kg>>7)*16384 + f*128 + (kg&127)];
            dst = (u32)(kg>>6)*8192 + (swz((u32)(f*128 + (kg&63)*2))>>1);
        } else {                                 // gate: nb in {r,z,i_n,h_n}
            int j = idx-65536, nb = j>>15, r = j&32767, f = r>>8, kg = r&255;
            float v = 0.f;
            if (nb==0) v = (kg<128) ? w_ih[f*128+kg]        : w_hh[f*128+kg-128];
            else if (nb==1) v = (kg<128) ? w_ih[(128+f)*128+kg] : w_hh[(128+f)*128+kg-128];
            else if (nb==2) v = (kg<128) ? w_ih[(256+f)*128+kg] : 0.f;
            else            v = (kg<128) ? 0.f : w_hh[(256+f)*128+kg-128];
            val = v;
            dst = 65536u + (u32)(nb*4 + (kg>>6))*8192 + (swz((u32)(f*128 + (kg&63)*2))>>1);
        }
        __half hh = __float2half_rn(val);
        if (idx < 65536) g_wch[dst] = __half_as_ushort(hh);
        else             g_wgh[dst-65536u] = __half_as_ushort(hh);
    }
}

// ---------------- init h ----------------
__global__ void __launch_bounds__(256) k_init(const float* __restrict__ hin){
    int tid = blockIdx.x*256+threadIdx.x;
    if (tid >= NN*64) return;
    float2 v = *(const float2*)&hin[tid*2];
    *(float2*)&g_h[tid*2] = v;
    u16 h0,l0,h1,l1; hl(v.x,h0,l0); hl(v.y,h1,l1);
    *(u32*)&g_hhi[tid*2] = (u32)h0 | ((u32)h1<<16);
    *(u32*)&g_hlo[tid*2] = (u32)l0 | ((u32)l1<<16);
}

// ---------------- CSR build over (dst,type) segments ----------------
__global__ void __launch_bounds__(256) k_hist(const int* __restrict__ dst,
    const int* __restrict__ ety){
    int e = blockIdx.x*256+threadIdx.x;
    if (e < NE) atomicAdd(&g_deg[dst[e]*4 + (ety[e]-1)], 1);
}
// block-level scan: each 1024-thread block scans 1024 elems
__global__ void __launch_bounds__(1024) k_scan1(){
    __shared__ int wsum[32];
    int t = threadIdx.x, lane = t&31, w = t>>5;
    int i = blockIdx.x*1024 + t;
    int v = (i<NSEG) ? g_deg[i] : 0;
    int s = v;
    #pragma unroll
    for (int o=1;o<32;o<<=1){ int u=__shfl_up_sync(~0u,s,o); if(lane>=o) s+=u; }
    if (lane==31) wsum[w]=s;
    __syncthreads();
    if (w==0){ int ws=wsum[lane];
        #pragma unroll
        for (int o=1;o<32;o<<=1){ int u=__shfl_up_sync(~0u,ws,o); if(lane>=o) ws+=u; }
        wsum[lane]=ws; }
    __syncthreads();
    int excl = s - v + (w>0 ? wsum[w-1] : 0);
    if (i<NSEG) g_roff[i] = excl;
    if (t==1023) g_bsum[blockIdx.x] = excl + v;
}
__global__ void __launch_bounds__(256) k_scan2(int nblk){
    __shared__ int wsum[8];
    int t = threadIdx.x, lane = t&31, w = t>>5;
    int v = (t<nblk) ? g_bsum[t] : 0;
    int s = v;
    #pragma unroll
    for (int o=1;o<32;o<<=1){ int u=__shfl_up_sync(~0u,s,o); if(lane>=o) s+=u; }
    if (lane==31) wsum[w]=s;
    __syncthreads();
    if (w==0 && lane<8){ int ws=wsum[lane];
        #pragma unroll
        for (int o=1;o<8;o<<=1){ int u=__shfl_up_sync(0xffu,ws,o); if(lane>=o) ws+=u; }
        wsum[lane]=ws; }
    __syncthreads();
    int excl = s - v + (w>0 ? wsum[w-1] : 0);
    if (t<nblk) g_boff[t] = excl;
}
__global__ void __launch_bounds__(256) k_scan3(){
    int i = blockIdx.x*256+threadIdx.x;
    if (i < NSEG){
        int r = g_roff[i] + g_boff[i>>10];
        g_roff[i] = r; g_cur[i] = r;
    }
    if (i == 0) g_roff[NSEG] = NE;
}
__global__ void __launch_bounds__(256) k_place(const int* __restrict__ src,
    const int* __restrict__ dst, const int* __restrict__ ety){
    int e = blockIdx.x*256+threadIdx.x;
    if (e >= NE) return;
    int pos = atomicAdd(&g_cur[dst[e]*4 + (ety[e]-1)], 1);
    g_srcs[pos] = src[e];
}

// ---------------- s-build: warp per (node,type) segment ----------------
__global__ void __launch_bounds__(256) k_sbuild(){
    int seg = (blockIdx.x*256+threadIdx.x)>>5, lane = threadIdx.x&31;
    if (seg >= NSEG) return;
    int beg = g_roff[seg], end = g_roff[seg+1];
    float4 a = {0,0,0,0};
    int e = beg;
    for (; e+1 < end; e += 2){
        int s0 = g_srcs[e], s1 = g_srcs[e+1];
        float4 v0 = *(const float4*)&g_h[(long)s0*128 + lane*4];
        float4 v1 = *(const float4*)&g_h[(long)s1*128 + lane*4];
        a.x += v0.x + v1.x; a.y += v0.y + v1.y;
        a.z += v0.z + v1.z; a.w += v0.w + v1.w;
    }
    if (e < end){
        float4 v = *(const float4*)&g_h[(long)g_srcs[e]*128 + lane*4];
        a.x += v.x; a.y += v.y; a.z += v.z; a.w += v.w;
    }
    int node = seg>>2, k = seg&3;
    long base = (long)node*512 + k*128 + lane*4;
    u16 h4[4], l4[4]; const float* f = (const float*)&a;
    #pragma unroll
    for (int i=0;i<4;i++) hl(f[i], h4[i], l4[i]);
    *(uint2*)&g_sh[base] = *(uint2*)h4;
    *(uint2*)&g_sl[base] = *(uint2*)l4;
    if (lane==0) g_cnt[seg] = (float)(end-beg);
}

// ---------------- GEMM A: a = s @ Wc^T (+cnt.b_lin) -> fp16 planes ----------------
__global__ void __launch_bounds__(256,2) k_gemm_a(const float* __restrict__ b_lin){
    extern __shared__ __align__(1024) char sm[];
    u32 sb = smem_u32(sm);
    int t = threadIdx.x, lane = t&31, wid = t>>5;
    int row0 = blockIdx.x*128;
    int wm = (wid&1)*64, wn = (wid>>1)*32;
    float cacc[4][4][4];
#pragma unroll
    for (int a=0;a<4;a++)
#pragma unroll
        for (int b=0;b<4;b++)
#pragma unroll
            for (int d=0;d<4;d++) cacc[a][b][d]=0.f;

    load_a_tile(sb, g_sh, g_sl, row0, 512, 0, t);
    load_b_tile(sb, g_wch, 0, t);
    CP_COMMIT();
    for (int c=0;c<8;c++){
        u32 st = sb + (u32)(c&1)*STAGE;
        if (c<7){
            u32 nx = sb + (u32)((c+1)&1)*STAGE;
            load_a_tile(nx, g_sh, g_sl, row0, 512, (c+1)*64, t);
            load_b_tile(nx, g_wch, c+1, t);
            CP_COMMIT();
            CP_WAIT1();
        } else CP_WAIT0();
        __syncthreads();
        compute_chunk(st, cacc, wm, wn, lane);
        __syncthreads();
    }
    // epilogue
    float* bls = (float*)sm;
    bls[t] = b_lin[t]; bls[t+256] = b_lin[256+t];
    __syncthreads();
    int tg = (lane&3)*2, gr = lane>>2;
#pragma unroll
    for (int mi=0;mi<4;mi++)
#pragma unroll
        for (int ni=0;ni<4;ni++){
            int col = wn + ni*8 + tg;
#pragma unroll
            for (int hf=0;hf<2;hf++){
                int r2 = row0 + wm + mi*16 + gr + hf*8;
                if (r2 < NN){
                    const float4 cn = *(const float4*)&g_cnt[r2*4];
                    float v0 = cacc[mi][ni][hf*2+0] + cn.x*bls[col]   + cn.y*bls[128+col]
                             + cn.z*bls[256+col]   + cn.w*bls[384+col];
                    float v1 = cacc[mi][ni][hf*2+1] + cn.x*bls[col+1] + cn.y*bls[129+col]
                             + cn.z*bls[257+col]   + cn.w*bls[385+col];
                    u16 h0,l0,h1,l1; hl(v0,h0,l0); hl(v1,h1,l1);
                    *(u32*)&g_ahi[(long)r2*128+col] = (u32)h0 | ((u32)h1<<16);
                    *(u32*)&g_alo[(long)r2*128+col] = (u32)l0 | ((u32)l1<<16);
                }
            }
        }
}

// ---------------- GEMM G: g[:, nb*128..] = [a|h] @ Wg[nb]^T ----------------
__global__ void __launch_bounds__(256,2) k_gemm_g(){
    extern __shared__ __align__(1024) char sm[];
    u32 sb = smem_u32(sm);
    int t = threadIdx.x, lane = t&31, wid = t>>5;
    int row0 = blockIdx.x*128;
    int nb = blockIdx.y;
    int c0 = (nb==3)?2:0, c1 = (nb==2)?2:4;
    int wm = (wid&1)*64, wn = (wid>>1)*32;
    float cacc[4][4][4];
#pragma unroll
    for (int a=0;a<4;a++)
#pragma unroll
        for (int b=0;b<4;b++)
#pragma unroll
            for (int d=0;d<4;d++) cacc[a][b][d]=0.f;

    {
        const u16* SH = (c0<2)? g_ahi : g_hhi;
        const u16* SL = (c0<2)? g_alo : g_hlo;
        load_a_tile(sb, SH, SL, row0, 128, (c0&1)*64, t);
        load_b_tile(sb, g_wgh, nb*4+c0, t);
        CP_COMMIT();
    }
    for (int c=c0;c<c1;c++){
        u32 st = sb + (u32)((c-c0)&1)*STAGE;
        if (c+1<c1){
            u32 nx = sb + (u32)((c+1-c0)&1)*STAGE;
            const u16* SH = (c+1<2)? g_ahi : g_hhi;
            const u16* SL = (c+1<2)? g_alo : g_hlo;
            load_a_tile(nx, SH, SL, row0, 128, ((c+1)&1)*64, t);
            load_b_tile(nx, g_wgh, nb*4+c+1, t);
            CP_COMMIT();
            CP_WAIT1();
        } else CP_WAIT0();
        __syncthreads();
        compute_chunk(st, cacc, wm, wn, lane);
        __syncthreads();
    }
    int tg = (lane&3)*2, gr = lane>>2;
#pragma unroll
    for (int mi=0;mi<4;mi++)
#pragma unroll
        for (int ni=0;ni<4;ni++){
            int col = wn + ni*8 + tg;
#pragma unroll
            for (int hf=0;hf<2;hf++){
                int r2 = row0 + wm + mi*16 + gr + hf*8;
                if (r2 < NN)
                    *(float2*)&g_g[(long)r2*512 + nb*128 + col] =
                        make_float2(cacc[mi][ni][hf*2+0], cacc[mi][ni][hf*2+1]);
            }
        }
}

// ---------------- GRU gates ----------------
__global__ void __launch_bounds__(256) k_gru(const float* __restrict__ b_ih,
    const float* __restrict__ b_hh, float* __restrict__ hout)
{
    int tid = blockIdx.x*256+threadIdx.x;
    if (tid >= NN*64) return;
    int row = tid>>6, p = (tid&63)*2;
    long gb = (long)row*512;
    float2 rp = *(const float2*)&g_g[gb + p];
    float2 zp = *(const float2*)&g_g[gb + 128 + p];
    float2 ip = *(const float2*)&g_g[gb + 256 + p];
    float2 hp = *(const float2*)&g_g[gb + 384 + p];
    float2 hv = *(const float2*)&g_h[(long)row*128 + p];

    float r0 = 1.f/(1.f + __expf(-(rp.x + b_ih[p]   + b_hh[p])));
    float r1 = 1.f/(1.f + __expf(-(rp.y + b_ih[p+1] + b_hh[p+1])));
    float z0 = 1.f/(1.f + __expf(-(zp.x + b_ih[128+p]   + b_hh[128+p])));
    float z1 = 1.f/(1.f + __expf(-(zp.y + b_ih[129+p] + b_hh[129+p])));
    float n0 = tanhf(ip.x + b_ih[256+p]   + r0*(hp.x + b_hh[256+p]));
    float n1 = tanhf(ip.y + b_ih[257+p] + r1*(hp.y + b_hh[257+p]));
    float o0 = (1.f-z0)*n0 + z0*hv.x;
    float o1 = (1.f-z1)*n1 + z1*hv.y;
    *(float2*)&hout[(long)row*128+p] = make_float2(o0,o1);
    u16 h0,l0,h1,l1; hl(o0,h0,l0); hl(o1,h1,l1);
    *(u32*)&g_hhi[(long)row*128+p] = (u32)h0 | ((u32)h1<<16);
    *(u32*)&g_hlo[(long)row*128+p] = (u32)l0 | ((u32)l1<<16);
}

// ---------------- launch ----------------
extern "C" void kernel_launch(void* const* d_in, const int* in_sizes, int n_in,
                              void* d_out, int out_size)
{
    const float* h_in  = (const float*)d_in[0];
    const int*   src   = (const int*)d_in[1];
    const int*   dst   = (const int*)d_in[2];
    const int*   ety   = (const int*)d_in[3];
    const float* W_lin = (const float*)d_in[4];
    const float* b_lin = (const float*)d_in[5];
    const float* w_ih  = (const float*)d_in[6];
    const float* w_hh  = (const float*)d_in[7];
    const float* b_ih  = (const float*)d_in[8];
    const float* b_hh  = (const float*)d_in[9];

    cudaFuncSetAttribute(k_gemm_a, cudaFuncAttributeMaxDynamicSharedMemorySize, SMB);
    cudaFuncSetAttribute(k_gemm_g, cudaFuncAttributeMaxDynamicSharedMemorySize, SMB);

    int* deg_p; cudaGetSymbolAddress((void**)&deg_p, g_deg);
    float* h_p; cudaGetSymbolAddress((void**)&h_p, g_h);

    const int scan_blocks = (NSEG + 1023) / 1024;   // 196

    k_setup<<<768,256>>>(W_lin, w_ih, w_hh);
    k_init<<<(NN*64+255)/256,256>>>(h_in);
    cudaMemsetAsync(deg_p, 0, NSEG*sizeof(int));
    k_hist<<<(NE+255)/256,256>>>(dst, ety);
    k_scan1<<<scan_blocks,1024>>>();
    k_scan2<<<1,256>>>(scan_blocks);
    k_scan3<<<(NSEG+255)/256,256>>>();
    k_place<<<(NE+255)/256,256>>>(src, dst, ety);

    const int tiles = (NN+127)/128;   // 391
    for (int step=0; step<NSTEP; step++){
        k_sbuild<<<(NSEG*32+255)/256,256>>>();
        k_gemm_a<<<tiles,256,SMB>>>(b_lin);
        k_gemm_g<<<dim3(tiles,4),256,SMB>>>();
        float* hout = (step==NSTEP-1) ? (float*)d_out : h_p;
        k_gru<<<(NN*64+255)/256,256>>>(b_ih, b_hh, hout);
    }
    (void)in_sizes; (void)n_in; (void)out_size;
}